// round 5
// baseline (speedup 1.0000x reference)
#include <cuda_runtime.h>
#include <cuda_bf16.h>
#include <math.h>
#include <stdint.h>

#define BSZ 8192
#define KN  32
#define DD  512

// ---------------------------------------------------------------------------
// Device scratch
// ---------------------------------------------------------------------------
__device__ __nv_bfloat16 g_Mth[DD * DD];   // bf16 hi of Mt[d][j] = sum_e w1[e][j] w2[e][d]
__device__ __nv_bfloat16 g_Mtl[DD * DD];   // bf16 lo
__device__ float g_q2[BSZ * DD];           // x @ M + c
__device__ float g_c[DD];                  // b1 @ w2
__device__ float g_u[DD];                  // b2 @ w1
__device__ float g_s0;                     // b1 . b2

// ---------------------------------------------------------------------------
// Helpers
// ---------------------------------------------------------------------------
__device__ __forceinline__ uint32_t smem_u32(const void* p) {
    uint32_t a;
    asm("{ .reg .u64 t; cvta.to.shared.u64 t, %1; cvt.u32.u64 %0, t; }"
        : "=r"(a) : "l"(p));
    return a;
}
__device__ __forceinline__ void cp16(uint32_t saddr, const void* g) {
    asm volatile("cp.async.cg.shared.global [%0], [%1], 16;"
                 :: "r"(saddr), "l"(g));
}
__device__ __forceinline__ void ldsm4(uint32_t* r, uint32_t addr) {
    asm volatile("ldmatrix.sync.aligned.m8n8.x4.shared.b16 {%0,%1,%2,%3}, [%4];"
                 : "=r"(r[0]), "=r"(r[1]), "=r"(r[2]), "=r"(r[3]) : "r"(addr));
}
__device__ __forceinline__ void mma16816(float* c, const uint32_t* a,
                                         uint32_t b0, uint32_t b1) {
    asm volatile(
        "mma.sync.aligned.m16n8k16.row.col.f32.bf16.bf16.f32 "
        "{%0,%1,%2,%3}, {%4,%5,%6,%7}, {%8,%9}, {%0,%1,%2,%3};"
        : "+f"(c[0]), "+f"(c[1]), "+f"(c[2]), "+f"(c[3])
        : "r"(a[0]), "r"(a[1]), "r"(a[2]), "r"(a[3]), "r"(b0), "r"(b1));
}

// ---------------------------------------------------------------------------
// precompute_all: Mt (bf16 split) + c + u + s0 in ONE kernel.
//   Mt[d][j] = sum_e w1[e][j] * w2[e][d]
//   u[j]     = sum_e b2[e] * w1[e][j]     (blocks with by==0, ty==0 row)
//   c[d]     = sum_e b1[e] * w2[e][d]     (blocks with bx==0, ty==1 row)
//   s0       = b1 . b2                    (block (0,0))
// ---------------------------------------------------------------------------
__global__ void precompute_all(const float* __restrict__ w1,
                               const float* __restrict__ w2,
                               const float* __restrict__ b1,
                               const float* __restrict__ b2) {
    __shared__ float s1[32][33];
    __shared__ float s2[32][33];
    __shared__ float sb1[DD], sb2[DD];
    int tx = threadIdx.x, ty = threadIdx.y;
    int tid = ty * 32 + tx;
    int j0 = blockIdx.x * 32, d0 = blockIdx.y * 32;
    if (tid < DD) { sb1[tid] = b1[tid]; sb2[tid] = b2[tid]; }

    float acc = 0.f;
    float uacc = 0.f, cacc = 0.f;
    for (int e0 = 0; e0 < DD; e0 += 32) {
        s1[ty][tx] = w1[(e0 + ty) * DD + j0 + tx];
        s2[ty][tx] = w2[(e0 + ty) * DD + d0 + tx];
        __syncthreads();
#pragma unroll
        for (int e = 0; e < 32; e++) acc += s1[e][tx] * s2[e][ty];
        if (blockIdx.y == 0 && ty == 0) {
#pragma unroll
            for (int e = 0; e < 32; e++) uacc += sb2[e0 + e] * s1[e][tx];
        }
        if (blockIdx.x == 0 && ty == 1) {
#pragma unroll
            for (int e = 0; e < 32; e++) cacc += sb1[e0 + e] * s2[e][tx];
        }
        __syncthreads();
    }
    __nv_bfloat16 hv = __float2bfloat16(acc);
    __nv_bfloat16 lv = __float2bfloat16(acc - __bfloat162float(hv));
    g_Mth[(d0 + ty) * DD + j0 + tx] = hv;
    g_Mtl[(d0 + ty) * DD + j0 + tx] = lv;
    if (blockIdx.y == 0 && ty == 0) g_u[j0 + tx] = uacc;
    if (blockIdx.x == 0 && ty == 1) g_c[d0 + tx] = cacc;
    if (blockIdx.x == 0 && blockIdx.y == 0 && ty == 2) {
        float v = 0.f;
#pragma unroll
        for (int q = 0; q < 16; q++) v += sb1[tx + 32 * q] * sb2[tx + 32 * q];
#pragma unroll
        for (int o = 16; o > 0; o >>= 1) v += __shfl_xor_sync(0xFFFFFFFFu, v, o);
        if (tx == 0) g_s0 = v;
    }
}

// ---------------------------------------------------------------------------
// Fused-split bf16x3 GEMM: q2 = x @ M + c over physical K=512 (16 k32 tiles).
// Block tile 64x256, 8 warps (2m x 4n), warp tile 32x64, 80B-padded rows.
// Grid (2, 128) = 256 blocks, 2 blocks/SM co-resident (smem 103KB).
// ---------------------------------------------------------------------------
#define NKT 16
#define XH_OFF 0
#define XL_OFF 5120
#define MH_OFF 10240
#define ML_OFF 30720
#define STAGE_STRIDE 51200
#define GSMEM_TOTAL (2 * STAGE_STRIDE + 1024)

__global__ __launch_bounds__(256) void gemm_fused(
    const float* __restrict__ x,
    const __nv_bfloat16* __restrict__ Mth, const __nv_bfloat16* __restrict__ Mtl,
    float* __restrict__ outf) {
    extern __shared__ char smem[];
    uint32_t sbase = smem_u32(smem);
    int tid = threadIdx.x;
    int lane = tid & 31;
    int warp = tid >> 5;
    int wm = warp >> 2;            // 0..1 (32-row warp tiles)
    int wn = warp & 3;             // 0..3 (64-col warp tiles)
    int bx = blockIdx.x, by = blockIdx.y;

    float* sb = (float*)(smem + 2 * STAGE_STRIDE);
    sb[tid] = g_c[bx * 256 + tid];

    float acc[2][8][4];
#pragma unroll
    for (int i = 0; i < 2; i++)
#pragma unroll
        for (int n = 0; n < 8; n++)
#pragma unroll
            for (int q = 0; q < 4; q++) acc[i][n][q] = 0.f;

    int arow  = lane & 15;
    int acol8 = (lane >> 4) * 8;
    int brow  = (lane & 7) + ((lane >> 4) << 3);
    int bcol8 = ((lane >> 3) & 1) * 8;

    // M tiles: 256 rows x 32 bf16 -> 4 cp16/row-group; 4 per thread per matrix
    auto load_M = [&](int stage, int kt) {
        int kk = kt * 32;
        uint32_t mh = sbase + stage * STAGE_STRIDE + MH_OFF;
        uint32_t ml = sbase + stage * STAGE_STRIDE + ML_OFF;
#pragma unroll
        for (int i = 0; i < 4; i++) {
            int c = tid + 256 * i;
            int n = c >> 2, q = c & 3;
            cp16(mh + n * 80 + q * 16,
                 Mth + (size_t)(bx * 256 + n) * DD + kk + q * 8);
            cp16(ml + n * 80 + q * 16,
                 Mtl + (size_t)(bx * 256 + n) * DD + kk + q * 8);
        }
        asm volatile("cp.async.commit_group;" ::: "memory");
    };

    // x: 64 rows x 32 floats = 512 float4 -> 2 per thread
    auto load_x_regs = [&](int kt, float4* vr) {
        int kk = kt * 32;
#pragma unroll
        for (int i = 0; i < 2; i++) {
            int c = tid + 256 * i;
            int r = c >> 3, q = c & 7;
            vr[i] = *(const float4*)(x + (size_t)(by * 64 + r) * DD + kk + q * 4);
        }
    };

    auto store_x = [&](int stage, const float4* vr) {
        uint32_t xh = stage * STAGE_STRIDE + XH_OFF;
        uint32_t xl = stage * STAGE_STRIDE + XL_OFF;
#pragma unroll
        for (int i = 0; i < 2; i++) {
            int c = tid + 256 * i;
            int r = c >> 3, q = c & 7;
            float4 v = vr[i];
            __nv_bfloat162 h01 = __floats2bfloat162_rn(v.x, v.y);
            __nv_bfloat162 h23 = __floats2bfloat162_rn(v.z, v.w);
            __nv_bfloat162 l01 = __floats2bfloat162_rn(v.x - __bfloat162float(h01.x),
                                                       v.y - __bfloat162float(h01.y));
            __nv_bfloat162 l23 = __floats2bfloat162_rn(v.z - __bfloat162float(h23.x),
                                                       v.w - __bfloat162float(h23.y));
            union { __nv_bfloat162 b[2]; uint2 u; } ph, pl;
            ph.b[0] = h01; ph.b[1] = h23;
            pl.b[0] = l01; pl.b[1] = l23;
            *(uint2*)(smem + xh + r * 80 + q * 8) = ph.u;
            *(uint2*)(smem + xl + r * 80 + q * 8) = pl.u;
        }
    };

    float4 xcur[2];
    load_x_regs(0, xcur);
    load_M(0, 0);
    store_x(0, xcur);

#pragma unroll 1
    for (int kt = 0; kt < NKT; kt++) {
        int cur = kt & 1;
        float4 xnext[2];
        if (kt + 1 < NKT) {
            load_x_regs(kt + 1, xnext);
            load_M(cur ^ 1, kt + 1);
            asm volatile("cp.async.wait_group 1;" ::: "memory");
        } else {
            asm volatile("cp.async.wait_group 0;" ::: "memory");
        }
        __syncthreads();

        uint32_t base = sbase + cur * STAGE_STRIDE;
#pragma unroll
        for (int h = 0; h < 2; h++) {
            uint32_t afh[2][4], afl[2][4];
#pragma unroll
            for (int i = 0; i < 2; i++) {
                uint32_t rowoff = (uint32_t)(wm * 32 + i * 16 + arow) * 80 +
                                  (uint32_t)(h * 16 + acol8) * 2;
                ldsm4(afh[i], base + XH_OFF + rowoff);
                ldsm4(afl[i], base + XL_OFF + rowoff);
            }
            uint32_t bfh[4][4], bfl[4][4];
#pragma unroll
            for (int j = 0; j < 4; j++) {
                uint32_t rowoff = (uint32_t)(wn * 64 + j * 16 + brow) * 80 +
                                  (uint32_t)(h * 16 + bcol8) * 2;
                ldsm4(bfh[j], base + MH_OFF + rowoff);
                ldsm4(bfl[j], base + ML_OFF + rowoff);
            }
#pragma unroll
            for (int i = 0; i < 2; i++)
#pragma unroll
                for (int j = 0; j < 4; j++) {
                    mma16816(acc[i][2 * j],     afh[i], bfh[j][0], bfh[j][1]);
                    mma16816(acc[i][2 * j + 1], afh[i], bfh[j][2], bfh[j][3]);
                    mma16816(acc[i][2 * j],     afh[i], bfl[j][0], bfl[j][1]);
                    mma16816(acc[i][2 * j + 1], afh[i], bfl[j][2], bfl[j][3]);
                    mma16816(acc[i][2 * j],     afl[i], bfh[j][0], bfh[j][1]);
                    mma16816(acc[i][2 * j + 1], afl[i], bfh[j][2], bfh[j][3]);
                }
        }
        if (kt + 1 < NKT) store_x(cur ^ 1, xnext);
        __syncthreads();
    }

    // epilogue: add bias, store fp32
    int g = lane >> 2, t4 = lane & 3;
#pragma unroll
    for (int i = 0; i < 2; i++) {
        int r0 = by * 64 + wm * 32 + i * 16 + g;
#pragma unroll
        for (int n = 0; n < 8; n++) {
            int coll = wn * 64 + n * 8 + 2 * t4;
            int colg = bx * 256 + coll;
            float bx0 = sb[coll], bx1 = sb[coll + 1];
            float2 v0 = make_float2(acc[i][n][0] + bx0, acc[i][n][1] + bx1);
            float2 v1 = make_float2(acc[i][n][2] + bx0, acc[i][n][3] + bx1);
            *(float2*)(outf + (size_t)r0 * DD + colg) = v0;
            *(float2*)(outf + (size_t)(r0 + 8) * DD + colg) = v1;
        }
    }
}

// ---------------------------------------------------------------------------
// Attend (unchanged): one warp per row, streams keys+values once. 81% DRAM.
// ---------------------------------------------------------------------------
__global__ __launch_bounds__(256) void attend(const float* __restrict__ x,
                                              const float* __restrict__ keys,
                                              const float* __restrict__ values,
                                              float* __restrict__ out) {
    int warp = (blockIdx.x * blockDim.x + threadIdx.x) >> 5;
    int lane = threadIdx.x & 31;
    if (warp >= BSZ) return;

    const float4* xr  = (const float4*)(x + (size_t)warp * DD);
    const float4* q2r = (const float4*)(g_q2 + (size_t)warp * DD);
    const float4* kb  = (const float4*)(keys + (size_t)warp * KN * DD);
    const float4* vb  = (const float4*)(values + (size_t)warp * KN * DD);
    const float4* ur  = (const float4*)g_u;

    float4 xv[4], qv[4];
#pragma unroll
    for (int i = 0; i < 4; i++) {
        xv[i] = xr[lane + 32 * i];
        qv[i] = q2r[lane + 32 * i];
    }

    float qb = 0.f;
#pragma unroll
    for (int i = 0; i < 4; i++) {
        float4 uv = ur[lane + 32 * i];
        qb += xv[i].x * uv.x + xv[i].y * uv.y + xv[i].z * uv.z + xv[i].w * uv.w;
    }
#pragma unroll
    for (int o = 16; o > 0; o >>= 1) qb += __shfl_xor_sync(0xFFFFFFFFu, qb, o);
    qb += g_s0;

    const float scale = 0.044194173824159216f;  // 1/sqrt(512)

    float myscore = 0.f;
    float4 cur[4];
#pragma unroll
    for (int i = 0; i < 4; i++) cur[i] = kb[lane + 32 * i];

#pragma unroll
    for (int k = 0; k < KN; k++) {
        float4 nxt[4];
        if (k + 1 < KN) {
#pragma unroll
            for (int i = 0; i < 4; i++) nxt[i] = kb[(k + 1) * 128 + lane + 32 * i];
        }
        float p = 0.f;
#pragma unroll
        for (int i = 0; i < 4; i++) {
            p += qv[i].x * cur[i].x + qv[i].y * cur[i].y +
                 qv[i].z * cur[i].z + qv[i].w * cur[i].w;
        }
#pragma unroll
        for (int o = 16; o > 0; o >>= 1) p += __shfl_xor_sync(0xFFFFFFFFu, p, o);
        float s = (p + qb) * scale;
        if (lane == k) myscore = s;
#pragma unroll
        for (int i = 0; i < 4; i++) cur[i] = nxt[i];
    }

    float m = myscore;
#pragma unroll
    for (int o = 16; o > 0; o >>= 1)
        m = fmaxf(m, __shfl_xor_sync(0xFFFFFFFFu, m, o));
    float e = expf(myscore - m);
    float sum = e;
#pragma unroll
    for (int o = 16; o > 0; o >>= 1) sum += __shfl_xor_sync(0xFFFFFFFFu, sum, o);
    float a = e / sum;

    float4 acc[4];
#pragma unroll
    for (int i = 0; i < 4; i++) acc[i] = make_float4(0.f, 0.f, 0.f, 0.f);

#pragma unroll
    for (int k = 0; k < KN; k++) {
        float w = __shfl_sync(0xFFFFFFFFu, a, k);
#pragma unroll
        for (int i = 0; i < 4; i++) {
            float4 vv = vb[k * 128 + lane + 32 * i];
            acc[i].x += w * vv.x;
            acc[i].y += w * vv.y;
            acc[i].z += w * vv.z;
            acc[i].w += w * vv.w;
        }
    }

    float4* outr = (float4*)(out + (size_t)warp * DD);
#pragma unroll
    for (int i = 0; i < 4; i++) {
        float4 o;
        o.x = 0.5f * xv[i].x + 0.5f * acc[i].x;
        o.y = 0.5f * xv[i].y + 0.5f * acc[i].y;
        o.z = 0.5f * xv[i].z + 0.5f * acc[i].z;
        o.w = 0.5f * xv[i].w + 0.5f * acc[i].w;
        outr[lane + 32 * i] = o;
    }
}

// ---------------------------------------------------------------------------
extern "C" void kernel_launch(void* const* d_in, const int* in_sizes, int n_in,
                              void* d_out, int out_size) {
    const float* x      = (const float*)d_in[0];
    const float* keys   = (const float*)d_in[1];
    const float* values = (const float*)d_in[2];
    const float* w1     = (const float*)d_in[3];
    const float* b1     = (const float*)d_in[4];
    const float* w2     = (const float*)d_in[5];
    const float* b2     = (const float*)d_in[6];
    float* out = (float*)d_out;

    cudaFuncSetAttribute(gemm_fused, cudaFuncAttributeMaxDynamicSharedMemorySize,
                         GSMEM_TOTAL);

    __nv_bfloat16 *Mth, *Mtl;
    float *q2;
    cudaGetSymbolAddress((void**)&Mth, g_Mth);
    cudaGetSymbolAddress((void**)&Mtl, g_Mtl);
    cudaGetSymbolAddress((void**)&q2, g_q2);

    precompute_all<<<dim3(16, 16), dim3(32, 32)>>>(w1, w2, b1, b2);
    gemm_fused<<<dim3(2, 128), 256, GSMEM_TOTAL>>>(x, Mth, Mtl, q2);
    attend<<<(BSZ * 32) / 256, 256>>>(x, keys, values, out);
}

// round 6
// speedup vs baseline: 1.1267x; 1.1267x over previous
#include <cuda_runtime.h>
#include <cuda_bf16.h>
#include <math.h>
#include <stdint.h>

#define BSZ 8192
#define KN  32
#define DD  512

// ---------------------------------------------------------------------------
// Device scratch
// ---------------------------------------------------------------------------
__device__ __nv_bfloat16 g_Mth[DD * DD];   // bf16 hi of Mt[d][j] = sum_e w1[e][j] w2[e][d]
__device__ __nv_bfloat16 g_Mtl[DD * DD];   // bf16 lo
__device__ float g_q2[BSZ * DD];           // x @ M + c
__device__ float g_c[DD];                  // b1 @ w2
__device__ float g_u[DD];                  // b2 @ w1
__device__ float g_s0;                     // b1 . b2

// ---------------------------------------------------------------------------
// Helpers
// ---------------------------------------------------------------------------
__device__ __forceinline__ uint32_t smem_u32(const void* p) {
    uint32_t a;
    asm("{ .reg .u64 t; cvta.to.shared.u64 t, %1; cvt.u32.u64 %0, t; }"
        : "=r"(a) : "l"(p));
    return a;
}
__device__ __forceinline__ void cp16(uint32_t saddr, const void* g) {
    asm volatile("cp.async.cg.shared.global [%0], [%1], 16;"
                 :: "r"(saddr), "l"(g));
}
__device__ __forceinline__ void ldsm4(uint32_t* r, uint32_t addr) {
    asm volatile("ldmatrix.sync.aligned.m8n8.x4.shared.b16 {%0,%1,%2,%3}, [%4];"
                 : "=r"(r[0]), "=r"(r[1]), "=r"(r[2]), "=r"(r[3]) : "r"(addr));
}
__device__ __forceinline__ void mma16816(float* c, const uint32_t* a,
                                         uint32_t b0, uint32_t b1) {
    asm volatile(
        "mma.sync.aligned.m16n8k16.row.col.f32.bf16.bf16.f32 "
        "{%0,%1,%2,%3}, {%4,%5,%6,%7}, {%8,%9}, {%0,%1,%2,%3};"
        : "+f"(c[0]), "+f"(c[1]), "+f"(c[2]), "+f"(c[3])
        : "r"(a[0]), "r"(a[1]), "r"(a[2]), "r"(a[3]), "r"(b0), "r"(b1));
}

// ---------------------------------------------------------------------------
// precompute_all: register-tiled fp32 GEMM (64x64 tile, 4x4 per thread) for
//   Mt[d][j] = sum_e w1[e][j] * w2[e][d]  -> bf16 hi/lo split store
// plus fused border reductions:
//   u[j] = sum_e b2[e] w1[e][j]  (blocks by==0, threads < 64)
//   c[d] = sum_e b1[e] w2[e][d]  (blocks bx==0, threads 64..127)
//   s0   = b1 . b2               (block (0,0))
// Grid (8, 8), 256 threads.
// ---------------------------------------------------------------------------
__global__ __launch_bounds__(256) void precompute_all(
    const float* __restrict__ w1, const float* __restrict__ w2,
    const float* __restrict__ b1, const float* __restrict__ b2) {
    __shared__ float s1[32][64];   // w1 tile [e][j]
    __shared__ float s2[32][64];   // w2 tile [e][d]
    __shared__ float sb1[DD], sb2[DD];
    int tid = threadIdx.x;
    int tc = tid & 15;             // j quad
    int tr = tid >> 4;             // d quad
    int j0 = blockIdx.x * 64, d0 = blockIdx.y * 64;

    sb1[tid] = b1[tid]; sb1[tid + 256] = b1[tid + 256];
    sb2[tid] = b2[tid]; sb2[tid + 256] = b2[tid + 256];
    __syncthreads();

    if (blockIdx.x == 0 && blockIdx.y == 0 && tid < 32) {
        float v = 0.f;
#pragma unroll
        for (int q = 0; q < 16; q++) v += sb1[tid + 32 * q] * sb2[tid + 32 * q];
#pragma unroll
        for (int o = 16; o > 0; o >>= 1) v += __shfl_xor_sync(0xFFFFFFFFu, v, o);
        if (tid == 0) g_s0 = v;
    }

    float acc[4][4];
#pragma unroll
    for (int r = 0; r < 4; r++)
#pragma unroll
        for (int c = 0; c < 4; c++) acc[r][c] = 0.f;
    float uacc = 0.f, cacc = 0.f;

    int lrow = tid >> 4;           // 0..15 (load row base within 32, two halves)
    int lq = tid & 15;             // float4 index within 64-float row

    for (int e0 = 0; e0 < DD; e0 += 32) {
#pragma unroll
        for (int i = 0; i < 2; i++) {
            int row = lrow + 16 * i;
            *(float4*)&s1[row][lq * 4] =
                *(const float4*)(w1 + (size_t)(e0 + row) * DD + j0 + lq * 4);
            *(float4*)&s2[row][lq * 4] =
                *(const float4*)(w2 + (size_t)(e0 + row) * DD + d0 + lq * 4);
        }
        __syncthreads();
#pragma unroll
        for (int e = 0; e < 32; e++) {
            float4 bv = *(const float4*)&s1[e][tc * 4];
            float4 av = *(const float4*)&s2[e][tr * 4];
            float br[4] = {bv.x, bv.y, bv.z, bv.w};
            float ar[4] = {av.x, av.y, av.z, av.w};
#pragma unroll
            for (int r = 0; r < 4; r++)
#pragma unroll
                for (int c = 0; c < 4; c++) acc[r][c] += ar[r] * br[c];
        }
        if (blockIdx.y == 0 && tid < 64) {
#pragma unroll
            for (int e = 0; e < 32; e++) uacc += sb2[e0 + e] * s1[e][tid];
        }
        if (blockIdx.x == 0 && tid >= 64 && tid < 128) {
#pragma unroll
            for (int e = 0; e < 32; e++) cacc += sb1[e0 + e] * s2[e][tid - 64];
        }
        __syncthreads();
    }

    // store bf16 hi/lo: rows d0+tr*4+r, cols j0+tc*4..+3
#pragma unroll
    for (int r = 0; r < 4; r++) {
        int d = d0 + tr * 4 + r;
        __nv_bfloat16 hv[4], lv[4];
#pragma unroll
        for (int c = 0; c < 4; c++) {
            hv[c] = __float2bfloat16(acc[r][c]);
            lv[c] = __float2bfloat16(acc[r][c] - __bfloat162float(hv[c]));
        }
        *(uint2*)&g_Mth[(size_t)d * DD + j0 + tc * 4] = *(uint2*)hv;
        *(uint2*)&g_Mtl[(size_t)d * DD + j0 + tc * 4] = *(uint2*)lv;
    }
    if (blockIdx.y == 0 && tid < 64) g_u[j0 + tid] = uacc;
    if (blockIdx.x == 0 && tid >= 64 && tid < 128) g_c[d0 + tid - 64] = cacc;
}

// ---------------------------------------------------------------------------
// Fused-split bf16x3 GEMM (R4 config): q2 = x @ M + c, K=512 (16 k32 tiles).
// Block tile 128x256, 8 warps (2m x 4n), warp tile 64x64, 80B-padded rows.
// ---------------------------------------------------------------------------
#define NKT 16
#define XH_OFF 0
#define XL_OFF 10240
#define MH_OFF 20480
#define ML_OFF 40960
#define STAGE_STRIDE 61440
#define GSMEM_TOTAL (2 * STAGE_STRIDE + 1024)

__global__ __launch_bounds__(256) void gemm_fused(
    const float* __restrict__ x,
    const __nv_bfloat16* __restrict__ Mth, const __nv_bfloat16* __restrict__ Mtl,
    float* __restrict__ outf) {
    extern __shared__ char smem[];
    uint32_t sbase = smem_u32(smem);
    int tid = threadIdx.x;
    int lane = tid & 31;
    int warp = tid >> 5;
    int wm = warp >> 2;
    int wn = warp & 3;
    int bx = blockIdx.x, by = blockIdx.y;

    float* sb = (float*)(smem + 2 * STAGE_STRIDE);
    sb[tid] = g_c[bx * 256 + tid];

    float acc[4][8][4];
#pragma unroll
    for (int i = 0; i < 4; i++)
#pragma unroll
        for (int n = 0; n < 8; n++)
#pragma unroll
            for (int q = 0; q < 4; q++) acc[i][n][q] = 0.f;

    int arow  = lane & 15;
    int acol8 = (lane >> 4) * 8;
    int brow  = (lane & 7) + ((lane >> 4) << 3);
    int bcol8 = ((lane >> 3) & 1) * 8;

    auto load_M = [&](int stage, int kt) {
        int kk = kt * 32;
        uint32_t mh = sbase + stage * STAGE_STRIDE + MH_OFF;
        uint32_t ml = sbase + stage * STAGE_STRIDE + ML_OFF;
#pragma unroll
        for (int i = 0; i < 4; i++) {
            int c = tid + 256 * i;
            int n = c >> 2, q = c & 3;
            cp16(mh + n * 80 + q * 16,
                 Mth + (size_t)(bx * 256 + n) * DD + kk + q * 8);
            cp16(ml + n * 80 + q * 16,
                 Mtl + (size_t)(bx * 256 + n) * DD + kk + q * 8);
        }
        asm volatile("cp.async.commit_group;" ::: "memory");
    };

    auto load_x_regs = [&](int kt, float4* vr) {
        int kk = kt * 32;
#pragma unroll
        for (int i = 0; i < 2; i++) {
            int c = tid + 256 * i;
            int r = c >> 2, q = c & 3;
            vr[i] = *(const float4*)(x + (size_t)(by * 128 + r) * DD + kk + q * 8);
            vr[i + 2] = *(const float4*)(x + (size_t)(by * 128 + r) * DD + kk + q * 8 + 4);
        }
    };

    auto store_x = [&](int stage, const float4* vr) {
        uint32_t xh = stage * STAGE_STRIDE + XH_OFF;
        uint32_t xl = stage * STAGE_STRIDE + XL_OFF;
#pragma unroll
        for (int i = 0; i < 2; i++) {
            int c = tid + 256 * i;
            int r = c >> 2, q = c & 3;
            float4 v0 = vr[i], v1 = vr[i + 2];
            __nv_bfloat162 h01 = __floats2bfloat162_rn(v0.x, v0.y);
            __nv_bfloat162 h23 = __floats2bfloat162_rn(v0.z, v0.w);
            __nv_bfloat162 h45 = __floats2bfloat162_rn(v1.x, v1.y);
            __nv_bfloat162 h67 = __floats2bfloat162_rn(v1.z, v1.w);
            __nv_bfloat162 l01 = __floats2bfloat162_rn(v0.x - __bfloat162float(h01.x),
                                                       v0.y - __bfloat162float(h01.y));
            __nv_bfloat162 l23 = __floats2bfloat162_rn(v0.z - __bfloat162float(h23.x),
                                                       v0.w - __bfloat162float(h23.y));
            __nv_bfloat162 l45 = __floats2bfloat162_rn(v1.x - __bfloat162float(h45.x),
                                                       v1.y - __bfloat162float(h45.y));
            __nv_bfloat162 l67 = __floats2bfloat162_rn(v1.z - __bfloat162float(h67.x),
                                                       v1.w - __bfloat162float(h67.y));
            union { __nv_bfloat162 b[4]; uint4 u; } ph, pl;
            ph.b[0] = h01; ph.b[1] = h23; ph.b[2] = h45; ph.b[3] = h67;
            pl.b[0] = l01; pl.b[1] = l23; pl.b[2] = l45; pl.b[3] = l67;
            *(uint4*)(smem + xh + r * 80 + q * 16) = ph.u;
            *(uint4*)(smem + xl + r * 80 + q * 16) = pl.u;
        }
    };

    float4 xcur[4];
    load_x_regs(0, xcur);
    load_M(0, 0);
    store_x(0, xcur);

#pragma unroll 1
    for (int kt = 0; kt < NKT; kt++) {
        int cur = kt & 1;
        float4 xnext[4];
        if (kt + 1 < NKT) {
            load_x_regs(kt + 1, xnext);
            load_M(cur ^ 1, kt + 1);
            asm volatile("cp.async.wait_group 1;" ::: "memory");
        } else {
            asm volatile("cp.async.wait_group 0;" ::: "memory");
        }
        __syncthreads();

        uint32_t base = sbase + cur * STAGE_STRIDE;
#pragma unroll
        for (int h = 0; h < 2; h++) {
            uint32_t afh[4][4], afl[4][4];
#pragma unroll
            for (int i = 0; i < 4; i++) {
                uint32_t rowoff = (uint32_t)(wm * 64 + i * 16 + arow) * 80 +
                                  (uint32_t)(h * 16 + acol8) * 2;
                ldsm4(afh[i], base + XH_OFF + rowoff);
                ldsm4(afl[i], base + XL_OFF + rowoff);
            }
            uint32_t bfh[4][4], bfl[4][4];
#pragma unroll
            for (int j = 0; j < 4; j++) {
                uint32_t rowoff = (uint32_t)(wn * 64 + j * 16 + brow) * 80 +
                                  (uint32_t)(h * 16 + bcol8) * 2;
                ldsm4(bfh[j], base + MH_OFF + rowoff);
                ldsm4(bfl[j], base + ML_OFF + rowoff);
            }
#pragma unroll
            for (int i = 0; i < 4; i++)
#pragma unroll
                for (int j = 0; j < 4; j++) {
                    mma16816(acc[i][2 * j],     afh[i], bfh[j][0], bfh[j][1]);
                    mma16816(acc[i][2 * j + 1], afh[i], bfh[j][2], bfh[j][3]);
                    mma16816(acc[i][2 * j],     afh[i], bfl[j][0], bfl[j][1]);
                    mma16816(acc[i][2 * j + 1], afh[i], bfl[j][2], bfl[j][3]);
                    mma16816(acc[i][2 * j],     afl[i], bfh[j][0], bfh[j][1]);
                    mma16816(acc[i][2 * j + 1], afl[i], bfh[j][2], bfh[j][3]);
                }
        }
        if (kt + 1 < NKT) store_x(cur ^ 1, xnext);
        __syncthreads();
    }

    int g = lane >> 2, t4 = lane & 3;
#pragma unroll
    for (int i = 0; i < 4; i++) {
        int r0 = by * 128 + wm * 64 + i * 16 + g;
#pragma unroll
        for (int n = 0; n < 8; n++) {
            int coll = wn * 64 + n * 8 + 2 * t4;
            int colg = bx * 256 + coll;
            float bx0 = sb[coll], bx1 = sb[coll + 1];
            float2 v0 = make_float2(acc[i][n][0] + bx0, acc[i][n][1] + bx1);
            float2 v1 = make_float2(acc[i][n][2] + bx0, acc[i][n][3] + bx1);
            *(float2*)(outf + (size_t)r0 * DD + colg) = v0;
            *(float2*)(outf + (size_t)(r0 + 8) * DD + colg) = v1;
        }
    }
}

// ---------------------------------------------------------------------------
// Attend (unchanged): one warp per row, streams keys+values once. 81% DRAM.
// ---------------------------------------------------------------------------
__global__ __launch_bounds__(256) void attend(const float* __restrict__ x,
                                              const float* __restrict__ keys,
                                              const float* __restrict__ values,
                                              float* __restrict__ out) {
    int warp = (blockIdx.x * blockDim.x + threadIdx.x) >> 5;
    int lane = threadIdx.x & 31;
    if (warp >= BSZ) return;

    const float4* xr  = (const float4*)(x + (size_t)warp * DD);
    const float4* q2r = (const float4*)(g_q2 + (size_t)warp * DD);
    const float4* kb  = (const float4*)(keys + (size_t)warp * KN * DD);
    const float4* vb  = (const float4*)(values + (size_t)warp * KN * DD);
    const float4* ur  = (const float4*)g_u;

    float4 xv[4], qv[4];
#pragma unroll
    for (int i = 0; i < 4; i++) {
        xv[i] = xr[lane + 32 * i];
        qv[i] = q2r[lane + 32 * i];
    }

    float qb = 0.f;
#pragma unroll
    for (int i = 0; i < 4; i++) {
        float4 uv = ur[lane + 32 * i];
        qb += xv[i].x * uv.x + xv[i].y * uv.y + xv[i].z * uv.z + xv[i].w * uv.w;
    }
#pragma unroll
    for (int o = 16; o > 0; o >>= 1) qb += __shfl_xor_sync(0xFFFFFFFFu, qb, o);
    qb += g_s0;

    const float scale = 0.044194173824159216f;  // 1/sqrt(512)

    float myscore = 0.f;
    float4 cur[4];
#pragma unroll
    for (int i = 0; i < 4; i++) cur[i] = kb[lane + 32 * i];

#pragma unroll
    for (int k = 0; k < KN; k++) {
        float4 nxt[4];
        if (k + 1 < KN) {
#pragma unroll
            for (int i = 0; i < 4; i++) nxt[i] = kb[(k + 1) * 128 + lane + 32 * i];
        }
        float p = 0.f;
#pragma unroll
        for (int i = 0; i < 4; i++) {
            p += qv[i].x * cur[i].x + qv[i].y * cur[i].y +
                 qv[i].z * cur[i].z + qv[i].w * cur[i].w;
        }
#pragma unroll
        for (int o = 16; o > 0; o >>= 1) p += __shfl_xor_sync(0xFFFFFFFFu, p, o);
        float s = (p + qb) * scale;
        if (lane == k) myscore = s;
#pragma unroll
        for (int i = 0; i < 4; i++) cur[i] = nxt[i];
    }

    float m = myscore;
#pragma unroll
    for (int o = 16; o > 0; o >>= 1)
        m = fmaxf(m, __shfl_xor_sync(0xFFFFFFFFu, m, o));
    float e = expf(myscore - m);
    float sum = e;
#pragma unroll
    for (int o = 16; o > 0; o >>= 1) sum += __shfl_xor_sync(0xFFFFFFFFu, sum, o);
    float a = e / sum;

    float4 acc[4];
#pragma unroll
    for (int i = 0; i < 4; i++) acc[i] = make_float4(0.f, 0.f, 0.f, 0.f);

#pragma unroll
    for (int k = 0; k < KN; k++) {
        float w = __shfl_sync(0xFFFFFFFFu, a, k);
#pragma unroll
        for (int i = 0; i < 4; i++) {
            float4 vv = vb[k * 128 + lane + 32 * i];
            acc[i].x += w * vv.x;
            acc[i].y += w * vv.y;
            acc[i].z += w * vv.z;
            acc[i].w += w * vv.w;
        }
    }

    float4* outr = (float4*)(out + (size_t)warp * DD);
#pragma unroll
    for (int i = 0; i < 4; i++) {
        float4 o;
        o.x = 0.5f * xv[i].x + 0.5f * acc[i].x;
        o.y = 0.5f * xv[i].y + 0.5f * acc[i].y;
        o.z = 0.5f * xv[i].z + 0.5f * acc[i].z;
        o.w = 0.5f * xv[i].w + 0.5f * acc[i].w;
        outr[lane + 32 * i] = o;
    }
}

// ---------------------------------------------------------------------------
extern "C" void kernel_launch(void* const* d_in, const int* in_sizes, int n_in,
                              void* d_out, int out_size) {
    const float* x      = (const float*)d_in[0];
    const float* keys   = (const float*)d_in[1];
    const float* values = (const float*)d_in[2];
    const float* w1     = (const float*)d_in[3];
    const float* b1     = (const float*)d_in[4];
    const float* w2     = (const float*)d_in[5];
    const float* b2     = (const float*)d_in[6];
    float* out = (float*)d_out;

    cudaFuncSetAttribute(gemm_fused, cudaFuncAttributeMaxDynamicSharedMemorySize,
                         GSMEM_TOTAL);

    __nv_bfloat16 *Mth, *Mtl;
    float *q2;
    cudaGetSymbolAddress((void**)&Mth, g_Mth);
    cudaGetSymbolAddress((void**)&Mtl, g_Mtl);
    cudaGetSymbolAddress((void**)&q2, g_q2);

    precompute_all<<<dim3(8, 8), 256>>>(w1, w2, b1, b2);
    gemm_fused<<<dim3(2, 64), 256, GSMEM_TOTAL>>>(x, Mth, Mtl, q2);
    attend<<<(BSZ * 32) / 256, 256>>>(x, keys, values, out);
}